// round 2
// baseline (speedup 1.0000x reference)
#include <cuda_runtime.h>
#include <cstdint>

#define N_NODES 4096
#define IN_F    128
#define HEADS   8
#define HIDDEN  8
#define OUTF    64   // HEADS*HIDDEN
#define SLOPE   0.2f

// Scratch (allocation-free rule: __device__ globals)
__device__ float g_feat[N_NODES * OUTF];   // 1 MB: projected features g
__device__ float g_sl[N_NODES * HEADS];    // 128 KB
__device__ float g_sr[N_NODES * HEADS];    // 128 KB

// ---------------------------------------------------------------------------
// Kernel 1: g = h @ W  (4096x128 @ 128x64), plus sl = g·a_l, sr = g·a_r per head
// Block: 256 threads = 4 nodes x 64 output cols. W staged in smem (32 KB).
// ---------------------------------------------------------------------------
__global__ void __launch_bounds__(256) proj_kernel(
    const float* __restrict__ h,
    const float* __restrict__ W,
    const float* __restrict__ a_l,
    const float* __restrict__ a_r)
{
    __shared__ float Ws[IN_F * OUTF];     // 32 KB
    __shared__ float hs[4][IN_F];         // 2 KB
    __shared__ float gs[4][OUTF];         // 1 KB

    const int tid = threadIdx.x;
    const int node0 = blockIdx.x * 4;

    for (int i = tid; i < IN_F * OUTF; i += 256) Ws[i] = W[i];
    for (int i = tid; i < 4 * IN_F; i += 256)
        hs[i >> 7][i & 127] = h[(size_t)(node0 + (i >> 7)) * IN_F + (i & 127)];
    __syncthreads();

    const int nl = tid >> 6;     // node within block, 0..3
    const int c  = tid & 63;     // output column
    float acc = 0.f;
    #pragma unroll 16
    for (int k = 0; k < IN_F; k++)
        acc = fmaf(hs[nl][k], Ws[k * OUTF + c], acc);

    const int node = node0 + nl;
    g_feat[(size_t)node * OUTF + c] = acc;
    gs[nl][c] = acc;
    __syncthreads();

    if (c < 8) {                       // head index c: compute sl
        float s = 0.f;
        #pragma unroll
        for (int d = 0; d < 8; d++) s = fmaf(gs[nl][c * 8 + d], a_l[d], s);
        g_sl[node * HEADS + c] = s;
    } else if (c < 16) {               // head index c-8: compute sr
        const int hh = c - 8;
        float s = 0.f;
        #pragma unroll
        for (int d = 0; d < 8; d++) s = fmaf(gs[nl][hh * 8 + d], a_r[d], s);
        g_sr[node * HEADS + hh] = s;
    }
}

// ---------------------------------------------------------------------------
// Kernel 2: one warp per destination row i. Adjacency is stored as 32-bit
// values (bool promoted by the harness; nonzero == edge, works for both
// int32 1 and float32 1.0f). Single-pass softmax (|e| < ~3, so exp() without
// max-subtraction is exact in fp32) fused with weighted aggregation of g[j].
// ---------------------------------------------------------------------------
__global__ void __launch_bounds__(256) attn_kernel(
    const unsigned int* __restrict__ adj,
    float* __restrict__ out)
{
    const int warp = threadIdx.x >> 5;
    const int lane = threadIdx.x & 31;
    const int row  = blockIdx.x * 8 + warp;

    // Broadcast sl[row][*] into registers (same addr all lanes -> L1 broadcast)
    float sl[HEADS];
    #pragma unroll
    for (int hh = 0; hh < HEADS; hh++) sl[hh] = g_sl[row * HEADS + hh];

    float acc[OUTF];
    #pragma unroll
    for (int k = 0; k < OUTF; k++) acc[k] = 0.f;
    float den[HEADS];
    #pragma unroll
    for (int hh = 0; hh < HEADS; hh++) den[hh] = 0.f;

    const uint4* __restrict__ arow =
        reinterpret_cast<const uint4*>(adj + (size_t)row * N_NODES);

    // 4096 words / (32 lanes * 4 words) = 32 iterations; double-buffered.
    uint4 v = arow[lane];
    #pragma unroll 1
    for (int t = 0; t < 32; t++) {
        uint4 vn;
        if (t < 31) vn = arow[(t + 1) * 32 + lane];
        if (v.x | v.y | v.z | v.w) {
            const int jbase = t * 128 + lane * 4;
            unsigned int words[4] = {v.x, v.y, v.z, v.w};
            #pragma unroll
            for (int wi = 0; wi < 4; wi++) {
                if (words[wi]) {
                    const int j = jbase + wi;
                    // attention logits for all 8 heads of edge (row <- j)
                    const float4* srp = reinterpret_cast<const float4*>(g_sr + j * HEADS);
                    float4 s0 = srp[0], s1 = srp[1];
                    float srj[8] = {s0.x, s0.y, s0.z, s0.w, s1.x, s1.y, s1.z, s1.w};
                    float w[HEADS];
                    #pragma unroll
                    for (int hh = 0; hh < HEADS; hh++) {
                        float e = sl[hh] + srj[hh];
                        e = (e >= 0.f) ? e : SLOPE * e;
                        float ww = __expf(e);
                        w[hh] = ww;
                        den[hh] += ww;
                    }
                    // accumulate w[h] * g[j][h*8+f]
                    const float4* gp = reinterpret_cast<const float4*>(g_feat + (size_t)j * OUTF);
                    #pragma unroll
                    for (int q = 0; q < 16; q++) {
                        float4 gv = gp[q];
                        const float wh = w[q >> 1];   // head = (q*4)/8
                        acc[q * 4 + 0] = fmaf(wh, gv.x, acc[q * 4 + 0]);
                        acc[q * 4 + 1] = fmaf(wh, gv.y, acc[q * 4 + 1]);
                        acc[q * 4 + 2] = fmaf(wh, gv.z, acc[q * 4 + 2]);
                        acc[q * 4 + 3] = fmaf(wh, gv.w, acc[q * 4 + 3]);
                    }
                }
            }
        }
        v = vn;
    }

    // Warp reduction: results land in lane 0 (static register indices only).
    #pragma unroll
    for (int k = 0; k < OUTF; k++) {
        #pragma unroll
        for (int off = 16; off >= 1; off >>= 1)
            acc[k] += __shfl_down_sync(0xFFFFFFFFu, acc[k], off);
    }
    #pragma unroll
    for (int hh = 0; hh < HEADS; hh++) {
        #pragma unroll
        for (int off = 16; off >= 1; off >>= 1)
            den[hh] += __shfl_down_sync(0xFFFFFFFFu, den[hh], off);
    }

    if (lane == 0) {
        float inv[HEADS];
        #pragma unroll
        for (int hh = 0; hh < HEADS; hh++) inv[hh] = 1.0f / den[hh];
        float4* op = reinterpret_cast<float4*>(out + (size_t)row * OUTF);
        #pragma unroll
        for (int q = 0; q < 16; q++) {
            const float iv = inv[q >> 1];
            op[q] = make_float4(acc[q * 4 + 0] * iv, acc[q * 4 + 1] * iv,
                                acc[q * 4 + 2] * iv, acc[q * 4 + 3] * iv);
        }
    }
}

// ---------------------------------------------------------------------------
extern "C" void kernel_launch(void* const* d_in, const int* in_sizes, int n_in,
                              void* d_out, int out_size)
{
    const float*        h   = (const float*)d_in[0];
    const unsigned int* adj = (const unsigned int*)d_in[1];
    const float*        W   = (const float*)d_in[2];
    const float*        a_l = (const float*)d_in[3];
    const float*        a_r = (const float*)d_in[4];
    float*              out = (float*)d_out;

    proj_kernel<<<N_NODES / 4, 256>>>(h, W, a_l, a_r);
    attn_kernel<<<N_NODES / 8, 256>>>(adj, out);
}

// round 3
// speedup vs baseline: 2.5963x; 2.5963x over previous
#include <cuda_runtime.h>
#include <cstdint>

#define N_NODES 4096
#define IN_F    128
#define HEADS   8
#define HIDDEN  8
#define OUTF    64   // HEADS*HIDDEN
#define SLOPE   0.2f
#define SEG     1024          // adjacency segment (nodes) per compaction pass
#define NSEG    (N_NODES / SEG)

// Scratch (allocation-free rule: __device__ globals)
__device__ float g_feat[N_NODES * OUTF];   // 1 MB: projected features g
__device__ float g_sl[N_NODES * HEADS];    // 128 KB
__device__ float g_sr[N_NODES * HEADS];    // 128 KB

// ---------------------------------------------------------------------------
// Kernel 1: g = h @ W  (4096x128 @ 128x64), plus sl = g·a_l, sr = g·a_r
// ---------------------------------------------------------------------------
__global__ void __launch_bounds__(256) proj_kernel(
    const float* __restrict__ h,
    const float* __restrict__ W,
    const float* __restrict__ a_l,
    const float* __restrict__ a_r)
{
    __shared__ float Ws[IN_F * OUTF];     // 32 KB
    __shared__ float hs[4][IN_F];
    __shared__ float gs[4][OUTF];

    const int tid = threadIdx.x;
    const int node0 = blockIdx.x * 4;

    for (int i = tid; i < IN_F * OUTF; i += 256) Ws[i] = W[i];
    for (int i = tid; i < 4 * IN_F; i += 256)
        hs[i >> 7][i & 127] = h[(size_t)(node0 + (i >> 7)) * IN_F + (i & 127)];
    __syncthreads();

    const int nl = tid >> 6;
    const int c  = tid & 63;
    float acc = 0.f;
    #pragma unroll 16
    for (int k = 0; k < IN_F; k++)
        acc = fmaf(hs[nl][k], Ws[k * OUTF + c], acc);

    const int node = node0 + nl;
    g_feat[(size_t)node * OUTF + c] = acc;
    gs[nl][c] = acc;
    __syncthreads();

    if (c < 8) {
        float s = 0.f;
        #pragma unroll
        for (int d = 0; d < 8; d++) s = fmaf(gs[nl][c * 8 + d], a_l[d], s);
        g_sl[node * HEADS + c] = s;
    } else if (c < 16) {
        const int hh = c - 8;
        float s = 0.f;
        #pragma unroll
        for (int d = 0; d < 8; d++) s = fmaf(gs[nl][hh * 8 + d], a_r[d], s);
        g_sr[node * HEADS + hh] = s;
    }
}

// ---------------------------------------------------------------------------
// Kernel 2: one warp per row. Phase A: ballot-compact edge indices into a
// per-warp smem list (warp-uniform). Phase B: all 32 lanes cooperatively
// process each edge; lane owns output floats {2*lane, 2*lane+1} (head=lane/4).
// den is redundantly identical across lanes of a head group -> no reductions.
// Single-pass softmax valid because |e| < ~3 (fp32-exact without max-sub).
// ---------------------------------------------------------------------------
__global__ void __launch_bounds__(256) attn_kernel(
    const unsigned int* __restrict__ adj,
    float* __restrict__ out)
{
    __shared__ uint16_t lists[8][SEG];    // 16 KB: per-warp edge index buffer

    const int warp = threadIdx.x >> 5;
    const int lane = threadIdx.x & 31;
    const int row  = blockIdx.x * 8 + warp;
    const unsigned lt_mask = (1u << lane) - 1u;

    uint16_t* list = lists[warp];

    const int head = lane >> 2;                    // this lane's head (2 floats)
    const float sl_h = g_sl[row * HEADS + head];   // broadcast within quad

    float acc0 = 0.f, acc1 = 0.f, den = 0.f;

    const uint4* __restrict__ arow =
        reinterpret_cast<const uint4*>(adj + (size_t)row * N_NODES);

    #pragma unroll 1
    for (int seg = 0; seg < NSEG; seg++) {
        // ---- Phase A: compact this segment's edges ----
        int cnt = 0;
        const uint4* base = arow + seg * (SEG / 4);
        #pragma unroll 1
        for (int st = 0; st < SEG / 128; st++) {       // 8 steps of 128 nodes
            uint4 v = base[st * 32 + lane];
            unsigned any = __ballot_sync(0xFFFFFFFFu, (v.x | v.y | v.z | v.w) != 0u);
            if (!any) continue;
            const int j0 = seg * SEG + st * 128 + lane * 4;
            unsigned b;
            b = __ballot_sync(0xFFFFFFFFu, v.x != 0u);
            if (v.x) list[cnt + __popc(b & lt_mask)] = (uint16_t)(j0 + 0);
            cnt += __popc(b);
            b = __ballot_sync(0xFFFFFFFFu, v.y != 0u);
            if (v.y) list[cnt + __popc(b & lt_mask)] = (uint16_t)(j0 + 1);
            cnt += __popc(b);
            b = __ballot_sync(0xFFFFFFFFu, v.z != 0u);
            if (v.z) list[cnt + __popc(b & lt_mask)] = (uint16_t)(j0 + 2);
            cnt += __popc(b);
            b = __ballot_sync(0xFFFFFFFFu, v.w != 0u);
            if (v.w) list[cnt + __popc(b & lt_mask)] = (uint16_t)(j0 + 3);
            cnt += __popc(b);
        }
        __syncwarp();

        // ---- Phase B: cooperative edge processing (unrolled x2 for MLP) ----
        int k = 0;
        #pragma unroll 1
        for (; k + 2 <= cnt; k += 2) {
            const int ja = list[k], jb = list[k + 1];
            const float2 ga = *reinterpret_cast<const float2*>(g_feat + ja * OUTF + lane * 2);
            const float2 gb = *reinterpret_cast<const float2*>(g_feat + jb * OUTF + lane * 2);
            const float sra = g_sr[ja * HEADS + head];
            const float srb = g_sr[jb * HEADS + head];

            float ea = sl_h + sra;  ea = fmaxf(ea, SLOPE * ea);
            float eb = sl_h + srb;  eb = fmaxf(eb, SLOPE * eb);
            const float wa = __expf(ea);
            const float wb = __expf(eb);
            den += wa + wb;
            acc0 = fmaf(wa, ga.x, acc0);
            acc1 = fmaf(wa, ga.y, acc1);
            acc0 = fmaf(wb, gb.x, acc0);
            acc1 = fmaf(wb, gb.y, acc1);
        }
        if (k < cnt) {
            const int j = list[k];
            const float2 gv = *reinterpret_cast<const float2*>(g_feat + j * OUTF + lane * 2);
            const float srj = g_sr[j * HEADS + head];
            float e = sl_h + srj;  e = fmaxf(e, SLOPE * e);
            const float w = __expf(e);
            den += w;
            acc0 = fmaf(w, gv.x, acc0);
            acc1 = fmaf(w, gv.y, acc1);
        }
        __syncwarp();
    }

    // Coalesced epilogue: each lane writes its two output floats.
    const float inv = 1.0f / den;
    float2* op = reinterpret_cast<float2*>(out + (size_t)row * OUTF) + lane;
    *op = make_float2(acc0 * inv, acc1 * inv);
}

// ---------------------------------------------------------------------------
extern "C" void kernel_launch(void* const* d_in, const int* in_sizes, int n_in,
                              void* d_out, int out_size)
{
    const float*        h   = (const float*)d_in[0];
    const unsigned int* adj = (const unsigned int*)d_in[1];
    const float*        W   = (const float*)d_in[2];
    const float*        a_l = (const float*)d_in[3];
    const float*        a_r = (const float*)d_in[4];
    float*              out = (float*)d_out;

    proj_kernel<<<N_NODES / 4, 256>>>(h, W, a_l, a_r);
    attn_kernel<<<N_NODES / 8, 256>>>(adj, out);
}

// round 4
// speedup vs baseline: 3.4297x; 1.3210x over previous
#include <cuda_runtime.h>
#include <cstdint>

#define N_NODES 4096
#define IN_F    128
#define HEADS   8
#define HIDDEN  8
#define OUTF    64   // HEADS*HIDDEN
#define SLOPE   0.2f
#define SEG     1024          // nodes per warp-quarter
#define NODES_PER_PROJ 16

// Scratch (allocation-free rule: __device__ globals)
__device__ float g_feat[N_NODES * OUTF];   // 1 MB
__device__ float g_sl[N_NODES * HEADS];    // 128 KB
__device__ float g_sr[N_NODES * HEADS];    // 128 KB

// ---------------------------------------------------------------------------
// Kernel 1: g = h @ W (4096x128 @ 128x64) + sl/sr head dots.
// 16 nodes per block, 256 threads, 4 outputs/thread (same column, 4 nodes).
// ---------------------------------------------------------------------------
__global__ void __launch_bounds__(256) proj_kernel(
    const float* __restrict__ h,
    const float* __restrict__ W,
    const float* __restrict__ a_l,
    const float* __restrict__ a_r)
{
    __shared__ float Ws[IN_F * OUTF];               // 32 KB
    __shared__ float hs[NODES_PER_PROJ][IN_F];      // 8 KB
    __shared__ float gs[NODES_PER_PROJ][OUTF];      // 4 KB

    const int tid   = threadIdx.x;
    const int node0 = blockIdx.x * NODES_PER_PROJ;

    for (int i = tid; i < IN_F * OUTF; i += 256) Ws[i] = W[i];
    for (int i = tid; i < NODES_PER_PROJ * IN_F; i += 256)
        hs[i >> 7][i & 127] = h[(size_t)node0 * IN_F + i];
    __syncthreads();

    const int c   = tid & 63;          // output column
    const int nb  = (tid >> 6) * 4;    // first of 4 nodes this thread computes
    float acc[4] = {0.f, 0.f, 0.f, 0.f};
    #pragma unroll 8
    for (int k = 0; k < IN_F; k++) {
        const float wv = Ws[k * OUTF + c];
        acc[0] = fmaf(hs[nb + 0][k], wv, acc[0]);
        acc[1] = fmaf(hs[nb + 1][k], wv, acc[1]);
        acc[2] = fmaf(hs[nb + 2][k], wv, acc[2]);
        acc[3] = fmaf(hs[nb + 3][k], wv, acc[3]);
    }
    #pragma unroll
    for (int q = 0; q < 4; q++) {
        g_feat[(size_t)(node0 + nb + q) * OUTF + c] = acc[q];
        gs[nb + q][c] = acc[q];
    }
    __syncthreads();

    // sl: threads 0..127 (node=tid>>3, head=tid&7); sr: threads 128..255
    const int t = tid & 127;
    const int nl = t >> 3, hh = t & 7;
    const float* av = (tid < 128) ? a_l : a_r;
    float s = 0.f;
    #pragma unroll
    for (int d = 0; d < 8; d++) s = fmaf(gs[nl][hh * 8 + d], av[d], s);
    if (tid < 128) g_sl[(node0 + nl) * HEADS + hh] = s;
    else           g_sr[(node0 + nl) * HEADS + hh] = s;
}

// ---------------------------------------------------------------------------
// Kernel 2: one block (4 warps) per destination row. Warp q owns nodes
// [q*1024, (q+1)*1024). Scan: all 8 LDG.128 front-batched (MLP=8, __ldcs
// streaming). Ballot-compact indices to smem, then cooperative edge
// processing: lane owns output floats {2*lane,2*lane+1}, head = lane/4.
// Partial (acc, den) per quarter combined in smem; softmax denominators add.
// Single-pass softmax exact since |e| < ~3 in fp32.
// ---------------------------------------------------------------------------
__global__ void __launch_bounds__(128) attn_kernel(
    const unsigned int* __restrict__ adj,
    float* __restrict__ out)
{
    __shared__ uint16_t lists[4][SEG];      // 8 KB
    __shared__ float part_acc[4][OUTF];     // 1 KB
    __shared__ float part_den[4][HEADS];    // 128 B

    const int warp = threadIdx.x >> 5;
    const int lane = threadIdx.x & 31;
    const int row  = blockIdx.x;
    const unsigned lt_mask = (1u << lane) - 1u;

    uint16_t* list = lists[warp];
    const int head = lane >> 2;
    const float sl_h = g_sl[row * HEADS + head];

    // ---- Scan: front-batch the whole 4 KB quarter (8 x LDG.128) ----
    const uint4* base = reinterpret_cast<const uint4*>(
        adj + (size_t)row * N_NODES) + warp * (SEG / 4);
    uint4 v[8];
    #pragma unroll
    for (int st = 0; st < 8; st++) v[st] = __ldcs(base + st * 32 + lane);

    // ---- Compact set positions into smem list ----
    int cnt = 0;
    #pragma unroll
    for (int st = 0; st < 8; st++) {
        const int j0 = warp * SEG + st * 128 + lane * 4;
        unsigned b;
        b = __ballot_sync(0xFFFFFFFFu, v[st].x != 0u);
        if (v[st].x) list[cnt + __popc(b & lt_mask)] = (uint16_t)(j0 + 0);
        cnt += __popc(b);
        b = __ballot_sync(0xFFFFFFFFu, v[st].y != 0u);
        if (v[st].y) list[cnt + __popc(b & lt_mask)] = (uint16_t)(j0 + 1);
        cnt += __popc(b);
        b = __ballot_sync(0xFFFFFFFFu, v[st].z != 0u);
        if (v[st].z) list[cnt + __popc(b & lt_mask)] = (uint16_t)(j0 + 2);
        cnt += __popc(b);
        b = __ballot_sync(0xFFFFFFFFu, v[st].w != 0u);
        if (v[st].w) list[cnt + __popc(b & lt_mask)] = (uint16_t)(j0 + 3);
        cnt += __popc(b);
    }
    __syncwarp();

    // ---- Cooperative edge processing (x2 unroll for MLP) ----
    float acc0 = 0.f, acc1 = 0.f, den = 0.f;
    int k = 0;
    #pragma unroll 1
    for (; k + 2 <= cnt; k += 2) {
        const int ja = list[k], jb = list[k + 1];
        const float2 ga = *reinterpret_cast<const float2*>(g_feat + ja * OUTF + lane * 2);
        const float2 gb = *reinterpret_cast<const float2*>(g_feat + jb * OUTF + lane * 2);
        const float sra = g_sr[ja * HEADS + head];
        const float srb = g_sr[jb * HEADS + head];
        float ea = sl_h + sra;  ea = fmaxf(ea, SLOPE * ea);
        float eb = sl_h + srb;  eb = fmaxf(eb, SLOPE * eb);
        const float wa = __expf(ea);
        const float wb = __expf(eb);
        den += wa + wb;
        acc0 = fmaf(wa, ga.x, acc0);
        acc1 = fmaf(wa, ga.y, acc1);
        acc0 = fmaf(wb, gb.x, acc0);
        acc1 = fmaf(wb, gb.y, acc1);
    }
    if (k < cnt) {
        const int j = list[k];
        const float2 gv = *reinterpret_cast<const float2*>(g_feat + j * OUTF + lane * 2);
        const float srj = g_sr[j * HEADS + head];
        float e = sl_h + srj;  e = fmaxf(e, SLOPE * e);
        const float w = __expf(e);
        den += w;
        acc0 = fmaf(w, gv.x, acc0);
        acc1 = fmaf(w, gv.y, acc1);
    }

    // ---- Combine quarters ----
    part_acc[warp][lane * 2 + 0] = acc0;
    part_acc[warp][lane * 2 + 1] = acc1;
    if ((lane & 3) == 0) part_den[warp][head] = den;
    __syncthreads();

    if (threadIdx.x < OUTF) {
        const int f = threadIdx.x;
        const float s = part_acc[0][f] + part_acc[1][f] +
                        part_acc[2][f] + part_acc[3][f];
        const int hh = f >> 3;
        const float d = part_den[0][hh] + part_den[1][hh] +
                        part_den[2][hh] + part_den[3][hh];
        out[(size_t)row * OUTF + f] = s / d;
    }
}

// ---------------------------------------------------------------------------
extern "C" void kernel_launch(void* const* d_in, const int* in_sizes, int n_in,
                              void* d_out, int out_size)
{
    const float*        h   = (const float*)d_in[0];
    const unsigned int* adj = (const unsigned int*)d_in[1];
    const float*        W   = (const float*)d_in[2];
    const float*        a_l = (const float*)d_in[3];
    const float*        a_r = (const float*)d_in[4];
    float*              out = (float*)d_out;

    proj_kernel<<<N_NODES / NODES_PER_PROJ, 256>>>(h, W, a_l, a_r);
    attn_kernel<<<N_NODES, 128>>>(adj, out);
}